// round 1
// baseline (speedup 1.0000x reference)
#include <cuda_runtime.h>
#include <math.h>

// Problem constants
#define BB 8
#define SS 2048
#define DD 1024
#define MTOT (BB * SS)   // 16384

// Scratch (device globals; no allocation allowed)
__device__ float g_q[(size_t)MTOT * DD];
__device__ float g_k[(size_t)MTOT * DD];
__device__ float g_v[(size_t)MTOT * DD];
__device__ float g_s[(size_t)BB * SS * SS];
__device__ float g_x[(size_t)MTOT * DD];

// ---------------------------------------------------------------------------
// Tiled SGEMM: C[m,n] = alpha * sum_k A[m,k] * B'[k,n]  (+ bias[n])
//   BT=true : B is N x K row-major (B'[k,n] = B[n,k])  -- "NT" (proj, Q K^T)
//   BT=false: B is K x N row-major                     -- "NN" (P V)
// BM=BN=128, BK=16, 256 threads, 8x8 per-thread microtile.
// All dims are multiples of the tile sizes for this problem -> no bounds checks.
// ---------------------------------------------------------------------------
template <bool BT, bool BIAS>
__global__ __launch_bounds__(256, 2)
void sgemm_kernel(const float* __restrict__ A,
                  const float* __restrict__ B,
                  const float* __restrict__ bias,
                  float* __restrict__ C,
                  int M, int N, int K, float alpha,
                  long sA, long sB, long sC)
{
    constexpr int BM = 128, BN = 128, BK = 16;
    __shared__ float As[BK][BM + 4];   // +4 pad keeps 16B alignment, breaks conflicts
    __shared__ float Bs[BK][BN + 4];

    const int tid = threadIdx.x;
    const int tx = tid & 15;        // 0..15 -> n
    const int ty = tid >> 4;        // 0..15 -> m
    const int bm = blockIdx.x * BM;
    const int bn = blockIdx.y * BN;

    A += (long)blockIdx.z * sA;
    B += (long)blockIdx.z * sB;
    C += (long)blockIdx.z * sC;

    float acc[8][8];
#pragma unroll
    for (int i = 0; i < 8; i++)
#pragma unroll
        for (int j = 0; j < 8; j++) acc[i][j] = 0.f;

    for (int k0 = 0; k0 < K; k0 += BK) {
        // ---- load A tile (BM x BK), transpose into As[k][m] ----
#pragma unroll
        for (int it = 0; it < 2; it++) {          // 512 float4 / 256 thr
            int idx = tid + it * 256;
            int r = idx >> 2, c4 = idx & 3;
            float4 v4 = *(const float4*)(A + (long)(bm + r) * K + k0 + c4 * 4);
            As[c4 * 4 + 0][r] = v4.x;
            As[c4 * 4 + 1][r] = v4.y;
            As[c4 * 4 + 2][r] = v4.z;
            As[c4 * 4 + 3][r] = v4.w;
        }
        // ---- load B tile ----
        if (BT) {
            // B rows bn..bn+BN, cols k0..k0+BK -> Bs[k][n]
#pragma unroll
            for (int it = 0; it < 2; it++) {
                int idx = tid + it * 256;
                int r = idx >> 2, c4 = idx & 3;
                float4 v4 = *(const float4*)(B + (long)(bn + r) * K + k0 + c4 * 4);
                Bs[c4 * 4 + 0][r] = v4.x;
                Bs[c4 * 4 + 1][r] = v4.y;
                Bs[c4 * 4 + 2][r] = v4.z;
                Bs[c4 * 4 + 3][r] = v4.w;
            }
        } else {
            // B rows k0..k0+BK, cols bn..bn+BN (contiguous along n)
#pragma unroll
            for (int it = 0; it < 2; it++) {
                int idx = tid + it * 256;
                int r = idx >> 5;           // /32 float4 per row
                int c4 = idx & 31;
                float4 v4 = *(const float4*)(B + (long)(k0 + r) * N + bn + c4 * 4);
                *(float4*)&Bs[r][c4 * 4] = v4;   // row stride 132*4=528B, 16B-aligned
            }
        }
        __syncthreads();

        // ---- compute ----
#pragma unroll
        for (int kk = 0; kk < BK; kk++) {
            float a[8], b[8];
#pragma unroll
            for (int j = 0; j < 8; j++) a[j] = As[kk][ty * 8 + j];
#pragma unroll
            for (int j = 0; j < 8; j++) b[j] = Bs[kk][tx * 8 + j];
#pragma unroll
            for (int i = 0; i < 8; i++)
#pragma unroll
                for (int j = 0; j < 8; j++)
                    acc[i][j] = fmaf(a[i], b[j], acc[i][j]);
        }
        __syncthreads();
    }

    // ---- epilogue ----
#pragma unroll
    for (int i = 0; i < 8; i++) {
        int row = bm + ty * 8 + i;
#pragma unroll
        for (int j = 0; j < 8; j += 4) {
            int col = bn + tx * 8 + j;
            float4 v4;
            v4.x = acc[i][j + 0] * alpha;
            v4.y = acc[i][j + 1] * alpha;
            v4.z = acc[i][j + 2] * alpha;
            v4.w = acc[i][j + 3] * alpha;
            if (BIAS) {
                v4.x += bias[col + 0];
                v4.y += bias[col + 1];
                v4.z += bias[col + 2];
                v4.w += bias[col + 3];
            }
            *(float4*)(C + (long)row * N + col) = v4;
        }
    }
}

// ---------------------------------------------------------------------------
// Row softmax over rows of length SS. One block (256 thr) per row.
// ---------------------------------------------------------------------------
__global__ __launch_bounds__(256)
void softmax_rows(float* __restrict__ s)
{
    float* p = s + (long)blockIdx.x * SS;
    const int tid = threadIdx.x;
    __shared__ float red[256];

    float local[8];
    float mx = -1e30f;
#pragma unroll
    for (int i = 0; i < 8; i++) {
        local[i] = p[tid + i * 256];
        mx = fmaxf(mx, local[i]);
    }
    red[tid] = mx;
    __syncthreads();
#pragma unroll
    for (int o = 128; o > 0; o >>= 1) {
        if (tid < o) red[tid] = fmaxf(red[tid], red[tid + o]);
        __syncthreads();
    }
    mx = red[0];
    __syncthreads();

    float sum = 0.f;
#pragma unroll
    for (int i = 0; i < 8; i++) {
        local[i] = __expf(local[i] - mx);
        sum += local[i];
    }
    red[tid] = sum;
    __syncthreads();
#pragma unroll
    for (int o = 128; o > 0; o >>= 1) {
        if (tid < o) red[tid] += red[tid + o];
        __syncthreads();
    }
    float inv = 1.f / red[0];
#pragma unroll
    for (int i = 0; i < 8; i++)
        p[tid + i * 256] = local[i] * inv;
}

// ---------------------------------------------------------------------------
extern "C" void kernel_launch(void* const* d_in, const int* in_sizes, int n_in,
                              void* d_out, int out_size)
{
    const float* query = (const float*)d_in[0];
    const float* key   = (const float*)d_in[1];
    const float* value = (const float*)d_in[2];
    const float* Wq = (const float*)d_in[3];
    const float* bq = (const float*)d_in[4];
    const float* Wk = (const float*)d_in[5];
    const float* bk = (const float*)d_in[6];
    const float* Wv = (const float*)d_in[7];
    const float* bv = (const float*)d_in[8];
    const float* Wo = (const float*)d_in[9];
    const float* bo = (const float*)d_in[10];
    float* out = (float*)d_out;

    float *q, *k, *v, *s, *x;
    cudaGetSymbolAddress((void**)&q, g_q);
    cudaGetSymbolAddress((void**)&k, g_k);
    cudaGetSymbolAddress((void**)&v, g_v);
    cudaGetSymbolAddress((void**)&s, g_s);
    cudaGetSymbolAddress((void**)&x, g_x);

    const dim3 blk(256);

    // Projections: [16384,1024] = X[16384,1024] @ W^T + b  (NT, bias)
    dim3 gp(MTOT / 128, DD / 128, 1);
    sgemm_kernel<true, true><<<gp, blk>>>(query, Wq, bq, q, MTOT, DD, DD, 1.f, 0, 0, 0);
    sgemm_kernel<true, true><<<gp, blk>>>(key,   Wk, bk, k, MTOT, DD, DD, 1.f, 0, 0, 0);
    sgemm_kernel<true, true><<<gp, blk>>>(value, Wv, bv, v, MTOT, DD, DD, 1.f, 0, 0, 0);

    // Scores: per batch, S = (Q K^T) / sqrt(128)   (NT, batched)
    const float alpha = 0.088388347648318447f;   // 1/sqrt(128)
    dim3 gs(SS / 128, SS / 128, BB);
    sgemm_kernel<true, false><<<gs, blk>>>(q, k, nullptr, s, SS, SS, DD, alpha,
                                           (long)SS * DD, (long)SS * DD, (long)SS * SS);

    // Softmax over rows
    softmax_rows<<<BB * SS, blk>>>(s);

    // X = P V  (NN, batched)
    dim3 gx(SS / 128, DD / 128, BB);
    sgemm_kernel<false, false><<<gx, blk>>>(s, v, nullptr, x, SS, DD, SS, 1.f,
                                            (long)SS * SS, (long)SS * DD, (long)SS * DD);

    // Output projection -> d_out
    sgemm_kernel<true, true><<<gp, blk>>>(x, Wo, bo, out, MTOT, DD, DD, 1.f, 0, 0, 0);
}